// round 1
// baseline (speedup 1.0000x reference)
#include <cuda_runtime.h>
#include <math.h>

// Problem shape (fixed by the dataset): N=100000, H=32, K=15, C_in=C_out=64
#define MAXN 100000
#define NB_H 32
#define KPTS 15
#define CH   64

// Scratch (allocation-free rule: __device__ globals)
__device__ float g_val[MAXN * CH];   // raw kpconv rows for active points
__device__ int   g_flag[MAXN];      // 1 if g_val row valid
__device__ float g_sum[CH];
__device__ float g_sumsq[CH];
__device__ float g_thresh;          // squared candidate radius
__device__ float g_mean[CH], g_inv[CH], g_z[CH];

static __host__ __device__ __forceinline__ float kp_extent() {
    return (float)(0.1 * 1.2 / 2.5);
}

// ---------------- init: zero flags/sums, compute candidate threshold ----------------
__global__ void init_kernel(const float* __restrict__ kp, int N) {
    int i = blockIdx.x * blockDim.x + threadIdx.x;
    if (i < N) g_flag[i] = 0;
    if (i < CH) { g_sum[i] = 0.0f; g_sumsq[i] = 0.0f; }
    if (i == 0) {
        float mx = 0.0f;
        for (int k = 0; k < KPTS; k++) {
            float a = kp[3*k], b = kp[3*k+1], c = kp[3*k+2];
            mx = fmaxf(mx, sqrtf(a*a + b*b + c*c));
        }
        float t = (kp_extent() + mx) * 1.0002f + 1e-6f;  // safety margin: false positives ok
        g_thresh = t * t;
    }
}

// ---------------- pass 1: detect active neighbors, exact KPConv for active rows ----------------
__global__ void __launch_bounds__(256) pass1_kernel(
    const float* __restrict__ q_pts,
    const float* __restrict__ s_pts,
    const int*   __restrict__ inds,
    const float* __restrict__ x,
    const float* __restrict__ kp,
    const float* __restrict__ W,   // [K, C, C]
    int N)
{
    __shared__ float sw[8][KPTS][CH];   // 30 KB

    const int warp = threadIdx.x >> 5;
    const int lane = threadIdx.x & 31;
    const int n = blockIdx.x * 8 + warp;
    if (n >= N) return;

    const float qx = __ldg(q_pts + 3*n);
    const float qy = __ldg(q_pts + 3*n + 1);
    const float qz = __ldg(q_pts + 3*n + 2);

    const int idx = __ldg(inds + n * NB_H + lane);
    const bool valid = ((unsigned)idx < (unsigned)N);
    float nx = 1e9f, ny = 1e9f, nz = 1e9f;
    if (valid) {
        nx = __ldg(s_pts + 3*idx)     - qx;
        ny = __ldg(s_pts + 3*idx + 1) - qy;
        nz = __ldg(s_pts + 3*idx + 2) - qz;
    }
    const float r2 = fmaf(nx, nx, fmaf(ny, ny, nz * nz));
    const float thr = g_thresh;

    const unsigned FULL = 0xffffffffu;
    unsigned mask = __ballot_sync(FULL, valid && (r2 < thr));
    if (mask == 0) return;   // ~99.99% of warps exit here

    // -------- heavy path (rare): exact reference math --------
    const float EXT  = kp_extent();
    const float EXT2 = EXT * EXT;
    const float INVE = 1.0f / EXT;

    float acc0[KPTS], acc1[KPTS];
#pragma unroll
    for (int k = 0; k < KPTS; k++) { acc0[k] = 0.0f; acc1[k] = 0.0f; }

    float kx[KPTS], ky[KPTS], kz[KPTS];
#pragma unroll
    for (int k = 0; k < KPTS; k++) {
        kx[k] = __ldg(kp + 3*k);
        ky[k] = __ldg(kp + 3*k + 1);
        kz[k] = __ldg(kp + 3*k + 2);
    }

    unsigned m = mask;
    while (m) {
        const int hs = __ffs(m) - 1;
        m &= (m - 1);
        const int   sidx = __shfl_sync(FULL, idx, hs);
        const float bx = __shfl_sync(FULL, nx, hs);
        const float by = __shfl_sync(FULL, ny, hs);
        const float bz = __shfl_sync(FULL, nz, hs);
        const float xv0 = __ldg(x + (long)sidx * CH + lane);
        const float xv1 = __ldg(x + (long)sidx * CH + lane + 32);
#pragma unroll
        for (int k = 0; k < KPTS; k++) {
            const float dx = bx - kx[k];
            const float dy = by - ky[k];
            const float dz = bz - kz[k];
            const float d2 = fmaf(dx, dx, fmaf(dy, dy, dz * dz));
            if (d2 < EXT2) {
                const float w = fmaxf(1.0f - sqrtf(d2) * INVE, 0.0f);
                acc0[k] = fmaf(w, xv0, acc0[k]);
                acc1[k] = fmaf(w, xv1, acc1[k]);
            }
        }
    }

    // stash weighted[k][c] in smem; track which k have any contribution
    unsigned kmask = 0;
#pragma unroll
    for (int k = 0; k < KPTS; k++) {
        sw[warp][k][lane]      = acc0[k];
        sw[warp][k][lane + 32] = acc1[k];
        if (__ballot_sync(FULL, (acc0[k] != 0.0f) || (acc1[k] != 0.0f)))
            kmask |= (1u << k);
    }
    __syncwarp();

    // out[d] = sum_{k,c} weighted[k,c] * W[k,c,d] ; lane owns d=lane, d=lane+32
    float o0 = 0.0f, o1 = 0.0f;
    for (int k = 0; k < KPTS; k++) {
        if (!(kmask & (1u << k))) continue;
        const float* Wk = W + (long)k * CH * CH;
#pragma unroll 8
        for (int c = 0; c < CH; c++) {
            const float wv = sw[warp][k][c];
            o0 = fmaf(wv, __ldg(Wk + c * CH + lane),      o0);
            o1 = fmaf(wv, __ldg(Wk + c * CH + lane + 32), o1);
        }
    }

    g_val[(long)n * CH + lane]      = o0;
    g_val[(long)n * CH + lane + 32] = o1;
    if (lane == 0) g_flag[n] = 1;
    atomicAdd(&g_sum[lane],        o0);
    atomicAdd(&g_sum[lane + 32],   o1);
    atomicAdd(&g_sumsq[lane],      o0 * o0);
    atomicAdd(&g_sumsq[lane + 32], o1 * o1);
}

// ---------------- pass 2: finalize stats, precompute normalized-zero per channel ----------------
__global__ void pass2_kernel(int N) {
    const int t = threadIdx.x;  // 64 threads
    const float invN = 1.0f / (float)N;
    const float mean = g_sum[t] * invN;
    const float var  = fmaxf(g_sumsq[t] * invN - mean * mean, 0.0f);
    const float inv  = rsqrtf(var + 1e-5f);
    const float z    = (0.0f - mean) * inv;
    g_mean[t] = mean;
    g_inv[t]  = inv;
    g_z[t]    = (z >= 0.0f) ? z : 0.1f * z;
}

// ---------------- pass 3: normalize + LeakyReLU, stream to d_out ----------------
__global__ void __launch_bounds__(256) pass3_kernel(float* __restrict__ out, int N) {
    __shared__ float zz[CH], mm[CH], iv[CH];
    const int t = threadIdx.x;
    if (t < CH) { zz[t] = g_z[t]; mm[t] = g_mean[t]; iv[t] = g_inv[t]; }
    __syncthreads();

    const int r = blockIdx.x * 16 + (t >> 4);   // 16 rows per block
    if (r >= N) return;
    const int j = (t & 15) * 4;                 // 16 threads * float4 = 64 channels

    float4 o;
    if (__ldg(&g_flag[r])) {
        const float4 v = *reinterpret_cast<const float4*>(g_val + (long)r * CH + j);
        float a = (v.x - mm[j])     * iv[j];
        float b = (v.y - mm[j + 1]) * iv[j + 1];
        float c = (v.z - mm[j + 2]) * iv[j + 2];
        float d = (v.w - mm[j + 3]) * iv[j + 3];
        o.x = (a >= 0.0f) ? a : 0.1f * a;
        o.y = (b >= 0.0f) ? b : 0.1f * b;
        o.z = (c >= 0.0f) ? c : 0.1f * c;
        o.w = (d >= 0.0f) ? d : 0.1f * d;
    } else {
        o = make_float4(zz[j], zz[j + 1], zz[j + 2], zz[j + 3]);
    }
    reinterpret_cast<float4*>(out)[(long)r * (CH / 4) + (t & 15)] = o;
}

// ---------------- launch ----------------
extern "C" void kernel_launch(void* const* d_in, const int* in_sizes, int n_in,
                              void* d_out, int out_size) {
    const float* q_pts = (const float*)d_in[0];
    const float* s_pts = (const float*)d_in[1];
    const int*   inds  = (const int*)  d_in[2];
    const float* x     = (const float*)d_in[3];
    const float* kp    = (const float*)d_in[4];
    const float* W     = (const float*)d_in[5];
    float* out = (float*)d_out;

    const int N = in_sizes[0] / 3;

    init_kernel<<<(N + 255) / 256, 256>>>(kp, N);
    pass1_kernel<<<(N + 7) / 8, 256>>>(q_pts, s_pts, inds, x, kp, W, N);
    pass2_kernel<<<1, CH>>>(N);
    pass3_kernel<<<(N + 15) / 16, 256>>>(out, N);
}